// round 13
// baseline (speedup 1.0000x reference)
#include <cuda_runtime.h>
#include <cuda_bf16.h>
#include <stdint.h>
#include <math.h>

// ---------------------------------------------------------------- constants
#define BATCH   2
#define NQ      16384
#define NATOMS  1024
#define KDIM    256
#define ODIM    256
#define NROWS   (BATCH * NQ)
#define OMEGA0  30.0f
#define EPSD    1e-4f

#define BM      64
#define BN      256
#define BKC     32
#define NCHUNK  (KDIM / BKC)     // 8
#define NTHREADS 512

#define OMEGA_CTAS 128
#define GEMM_CTAS  (NROWS / BM)  // 512

// SMEM map (all tiles: 32B rows, XOR bit7->bit4 swizzle)
// A: 2 stages x 8KB   [stage: slice0{hi2K,lo2K}, slice1{hi,lo}]
// B: 2 stages x 32KB  [stage: slice0{hi8K,lo8K}, slice1{hi,lo}]
// X: 2 stages x 8KB   (fp32 64x32, 128B rows, SW128)
#define OFF_A   0
#define OFF_B   16384
#define OFF_X   81920
#define A_ST    8192
#define B_ST    32768
#define X_ST    8192
#define SM_BYTES  98304
#define EPI_STRIDE 264
// omega path: 2 partitions x (512 float4 + 16B pad)
#define PAD_PART 8208

static __device__ __nv_bfloat16 g_Whi[ODIM * KDIM];
static __device__ __nv_bfloat16 g_Wlo[ODIM * KDIM];
static __device__ float         g_omega[NROWS];
static __device__ int           g_flag;

// ---------------------------------------------------------------- helpers
__device__ __forceinline__ uint32_t smem_u32(const void* p) {
    uint32_t a;
    asm("{ .reg .u64 t; cvta.to.shared.u64 t, %1; cvt.u32.u64 %0, t; }" : "=r"(a) : "l"(p));
    return a;
}
__device__ __forceinline__ uint32_t swz(uint32_t o)   { return o ^ ((o >> 3) & 0x70); }
__device__ __forceinline__ uint32_t swz32(uint32_t o) { return o ^ ((o >> 3) & 0x10); }

__device__ __forceinline__ void sts_u2(uint32_t a, uint32_t x, uint32_t y) {
    asm volatile("st.shared.v2.b32 [%0], {%1,%2};" :: "r"(a), "r"(x), "r"(y));
}
__device__ __forceinline__ void cp16(uint32_t dst, const void* src) {
    asm volatile("cp.async.cg.shared.global [%0], [%1], 16;" :: "r"(dst), "l"(src));
}
#define CP_COMMIT() asm volatile("cp.async.commit_group;")
#define CP_WAIT0()  asm volatile("cp.async.wait_group 0;")

#define LDSM4(r, a) \
    asm volatile("ldmatrix.sync.aligned.m8n8.x4.shared.b16 {%0,%1,%2,%3}, [%4];" \
        : "=r"((r)[0]), "=r"((r)[1]), "=r"((r)[2]), "=r"((r)[3]) : "r"(a))

__device__ __forceinline__ void mma_bf16(float* c, const uint32_t* a,
                                         uint32_t b0, uint32_t b1) {
    asm volatile(
        "mma.sync.aligned.m16n8k16.row.col.f32.bf16.bf16.f32 "
        "{%0,%1,%2,%3}, {%4,%5,%6,%7}, {%8,%9}, {%0,%1,%2,%3};"
        : "+f"(c[0]), "+f"(c[1]), "+f"(c[2]), "+f"(c[3])
        : "r"(a[0]), "r"(a[1]), "r"(a[2]), "r"(a[3]), "r"(b0), "r"(b1));
}
__device__ __forceinline__ uint32_t packsplit(float x, float y, uint32_t& lo) {
    uint32_t h;
    asm("cvt.rn.bf16x2.f32 %0, %1, %2;" : "=r"(h) : "f"(y), "f"(x));
    float hx = __uint_as_float(h << 16);
    float hy = __uint_as_float(h & 0xffff0000u);
    float rx = x - hx, ry = y - hy;
    asm("cvt.rn.bf16x2.f32 %0, %1, %2;" : "=r"(lo) : "f"(ry), "f"(rx));
    return h;
}

// ---------------------------------------------------------------- prep: W split + flag reset
__global__ __launch_bounds__(256)
void prep_w(const float* __restrict__ W)
{
    if (blockIdx.x == 0 && threadIdx.x == 0) g_flag = 0;
    int i = blockIdx.x * 256 + threadIdx.x;
    float w = W[i];
    __nv_bfloat16 h = __float2bfloat16(w);
    g_Whi[i] = h;
    g_Wlo[i] = __float2bfloat16(w - __bfloat162float(h));
}

// ---------------------------------------------------------------- main: omega CTAs + GEMM CTAs
__global__ __launch_bounds__(NTHREADS, 2)
void siren_main(const float* __restrict__ X, const float* __restrict__ Q,
                const float* __restrict__ atoms, const float* __restrict__ bias,
                const float* __restrict__ fw1, const float* __restrict__ fb1,
                const float* __restrict__ fw2, const float* __restrict__ fb2,
                float* __restrict__ out)
{
    extern __shared__ char sb[];
    const uint32_t sbase = smem_u32(sb);
    const int tid = threadIdx.x;

    // ================= omega CTAs (first wave) =================
    if (blockIdx.x < OMEGA_CTAS) {
        const int q0 = blockIdx.x * 256;
        const int batch = (q0 >= NQ) ? 1 : 0;
        const float* ab = atoms + (size_t)batch * NATOMS * 3;
        for (int j = tid; j < NATOMS; j += NTHREADS) {
            float ax = ab[3*j], ay = ab[3*j+1], az = ab[3*j+2];
            *(float4*)(sb + (j >> 9) * PAD_PART + (j & 511) * 16) =
                make_float4(ax, ay, az, fmaf(ax, ax, fmaf(ay, ay, az*az)));
        }
        __syncthreads();

        const int qi = q0 + (tid >> 1);
        const int part = tid & 1;
        const float* qp = Q + (size_t)qi * 3;
        float qx = qp[0], qy = qp[1], qz = qp[2];
        float nqx = -2.f * qx, nqy = -2.f * qy, nqz = -2.f * qz;
        const float4* at = (const float4*)(sb + part * PAD_PART);
        float m0 = 3.4e38f, m1 = 3.4e38f;
#pragma unroll 4
        for (int j = 0; j < 512; j += 2) {
            float4 a0 = at[j], a1 = at[j + 1];
            m0 = fminf(m0, fmaf(a0.x, nqx, fmaf(a0.y, nqy, fmaf(a0.z, nqz, a0.w))));
            m1 = fminf(m1, fmaf(a1.x, nqx, fmaf(a1.y, nqy, fmaf(a1.z, nqz, a1.w))));
        }
        float md = fminf(m0, m1);
        md = fminf(md, __shfl_xor_sync(0xffffffffu, md, 1));
        if (part == 0) {
            float qsq = fmaf(qx, qx, fmaf(qy, qy, qz * qz));
            float mind = sqrtf(fmaxf(md + qsq, EPSD));
            float ls = __ldg(fb2);
#pragma unroll
            for (int j = 0; j < 16; ++j) {
                float z = fmaf(__ldg(fw1 + 3*j), qx,
                          fmaf(__ldg(fw1 + 3*j + 1), qy,
                          fmaf(__ldg(fw1 + 3*j + 2), qz, __ldg(fb1 + j))));
                float sp = fmaxf(z, 0.0f) + log1pf(expf(-fabsf(z)));
                ls = fmaf(__ldg(fw2 + j), sp, ls);
            }
            ls = fminf(fmaxf(ls, 0.0f), 5.0f);
            g_omega[qi] = OMEGA0 * (1.0f + ls * expf(-mind));
        }
        __threadfence();
        __syncthreads();
        if (tid == 0) atomicAdd(&g_flag, 1);
        return;
    }

    // ================= GEMM CTAs: 64 rows x 256 cols =================
    const int bid  = blockIdx.x - OMEGA_CTAS;
    const int lane = tid & 31;
    const int wid  = tid >> 5;
    const int gRow0 = bid * BM;

    const int warpM = (wid & 3) * 16;        // 4 M-groups of 16
    const int warpN = (wid >> 2) * 64;       // 4 N-groups of 64
    const int lr = lane >> 2;
    const int lc = (lane & 3) * 2;
    const int l7 = lane & 7, g = lane >> 3;
    // A m16k16 ldsm.x4: rows warpM + l7 + (g&1)*8, byte half ((g>>1)&1)*16
    const uint32_t aoff = swz32((uint32_t)((warpM + l7 + (g & 1) * 8) * 32 + ((g >> 1) & 1) * 16));
    // B n16k16 ldsm.x4 per p-tile
    const uint32_t boff = swz32((uint32_t)((warpN + l7 + (g >> 1) * 8) * 32 + (g & 1) * 16));

    auto prefB = [&](int c) {   // 256 N-rows x K32 hi+lo -> stage c&1 (4 cp16/thread)
#pragma unroll
        for (int i = 0; i < 2; ++i) {
            int u = tid + i * NTHREADS;          // 0..1023
            int n = u >> 2, q = (u >> 1) & 1, e = u & 1;
            const uint32_t d0 = sbase + OFF_B + (uint32_t)(c & 1) * B_ST + q * 16384
                              + (swz32((uint32_t)(n * 32)) ^ (uint32_t)(e * 16));
            const int gs = n * KDIM + c * BKC + q * 16 + e * 8;
            cp16(d0,        g_Whi + gs);
            cp16(d0 + 8192, g_Wlo + gs);
        }
    };
    auto prefX = [&](int c) {   // fp32 64x32 -> X stage c&1 (1 cp16/thread)
        const uint32_t base = sbase + OFF_X + (uint32_t)(c & 1) * X_ST;
        const float* src = X + (size_t)gRow0 * KDIM + c * BKC;
        cp16(base + swz((uint32_t)tid * 16),
             src + (size_t)(tid >> 3) * KDIM + (tid & 7) * 4);
    };
    auto convertX = [&](int c) { // X stage -> A stage (hi/lo bf16), 4 floats/thread
        const char* xs = sb + OFF_X + (uint32_t)(c & 1) * X_ST;
        const int r = tid >> 3, seg = tid & 7;
        float4 v = *(const float4*)(xs + swz((uint32_t)(r * 128 + seg * 16)));
        uint32_t h0, h1, l0, l1;
        h0 = packsplit(v.x, v.y, l0);
        h1 = packsplit(v.z, v.w, l1);
        const uint32_t ab = sbase + OFF_A + (uint32_t)(c & 1) * A_ST + (seg >> 2) * 4096
                          + swz32((uint32_t)(r * 32 + (seg & 3) * 8));
        sts_u2(ab,        h0, h1);
        sts_u2(ab + 2048, l0, l1);
    };

    // ---- prologue ----
    prefX(0);
    prefX(1);
    prefB(0);
    CP_COMMIT();
    CP_WAIT0();
    __syncthreads();
    convertX(0);

    float acc[8][4];
#pragma unroll
    for (int j = 0; j < 8; ++j)
#pragma unroll
        for (int k = 0; k < 4; ++k) acc[j][k] = 0.0f;

    // ---- main loop (race-free schedule: wait -> barrier -> prefetch -> compute -> convert)
#pragma unroll 1
    for (int c = 0; c < NCHUNK; ++c) {
        CP_WAIT0();
        __syncthreads();
        if (c + 2 < NCHUNK) prefX(c + 2);
        if (c + 1 < NCHUNK) prefB(c + 1);
        CP_COMMIT();

        const uint32_t Ast = sbase + OFF_A + (uint32_t)(c & 1) * A_ST;
        const uint32_t Bst = sbase + OFF_B + (uint32_t)(c & 1) * B_ST;
#pragma unroll
        for (int s = 0; s < 2; ++s) {
            const uint32_t ab = Ast + s * 4096 + aoff;
            const uint32_t bb = Bst + s * 16384 + boff;
            uint32_t ah[4], al[4], bq[4][4];
            LDSM4(ah, ab);
            LDSM4(al, ab + 2048);
#pragma unroll
            for (int p = 0; p < 4; ++p) LDSM4(bq[p], bb + p * 512);
            // pass 1: hi*HI
#pragma unroll
            for (int p = 0; p < 4; ++p) {
                mma_bf16(acc[2*p],   ah, bq[p][0], bq[p][1]);
                mma_bf16(acc[2*p+1], ah, bq[p][2], bq[p][3]);
            }
            // pass 2: lo*HI
#pragma unroll
            for (int p = 0; p < 4; ++p) {
                mma_bf16(acc[2*p],   al, bq[p][0], bq[p][1]);
                mma_bf16(acc[2*p+1], al, bq[p][2], bq[p][3]);
            }
            // pass 3: hi*LO
#pragma unroll
            for (int p = 0; p < 4; ++p) LDSM4(bq[p], bb + 8192 + p * 512);
#pragma unroll
            for (int p = 0; p < 4; ++p) {
                mma_bf16(acc[2*p],   ah, bq[p][0], bq[p][1]);
                mma_bf16(acc[2*p+1], ah, bq[p][2], bq[p][3]);
            }
            if (s == 0 && c + 1 < NCHUNK) convertX(c + 1);
        }
    }
    __syncthreads();

    // ---- wait for omega CTAs ----
    if (tid == 0) {
        int v;
        do {
            asm volatile("ld.acquire.gpu.global.b32 %0, [%1];" : "=r"(v) : "l"(&g_flag));
        } while (v < OMEGA_CTAS);
    }
    __syncthreads();

    // ---- epilogue: sin(omega*(acc+bias)) -> SMEM -> coalesced STG ----
    float* stg = (float*)sb;
    {
        int r0 = warpM + lr;
        float o0 = __ldg(g_omega + gRow0 + r0);
        float o1 = __ldg(g_omega + gRow0 + r0 + 8);
#pragma unroll
        for (int nt = 0; nt < 8; ++nt) {
            int c0 = warpN + nt * 8 + lc;
            float b0 = __ldg(bias + c0), b1 = __ldg(bias + c0 + 1);
            float* a = acc[nt];
            *(float2*)(stg + r0 * EPI_STRIDE + c0) =
                make_float2(__sinf(o0 * (a[0] + b0)), __sinf(o0 * (a[1] + b1)));
            *(float2*)(stg + (r0 + 8) * EPI_STRIDE + c0) =
                make_float2(__sinf(o1 * (a[2] + b0)), __sinf(o1 * (a[3] + b1)));
        }
    }
    __syncthreads();
#pragma unroll
    for (int i = 0; i < 8; ++i) {
        int lin = tid + i * NTHREADS;          // float4 over 64x256
        int rr = lin >> 6, c4 = (lin & 63) * 4;
        *(float4*)(out + (size_t)(gRow0 + rr) * ODIM + c4) =
            *(const float4*)(stg + rr * EPI_STRIDE + c4);
    }
}

// ---------------------------------------------------------------- launch
extern "C" void kernel_launch(void* const* d_in, const int* in_sizes, int n_in,
                              void* d_out, int out_size)
{
    const float* x     = (const float*)d_in[0];
    const float* q     = (const float*)d_in[1];
    const float* atoms = (const float*)d_in[2];
    const float* W     = (const float*)d_in[3];
    const float* bias  = (const float*)d_in[4];
    const float* fw1   = (const float*)d_in[5];
    const float* fb1   = (const float*)d_in[6];
    const float* fw2   = (const float*)d_in[7];
    const float* fb2   = (const float*)d_in[8];
    float* out = (float*)d_out;
    (void)in_sizes; (void)n_in; (void)out_size;

    cudaFuncSetAttribute(siren_main, cudaFuncAttributeMaxDynamicSharedMemorySize, SM_BYTES);

    prep_w<<<(ODIM * KDIM) / 256, 256>>>(W);
    siren_main<<<OMEGA_CTAS + GEMM_CTAS, NTHREADS, SM_BYTES>>>(
        x, q, atoms, bias, fw1, fb1, fw2, fb2, out);
}